// round 3
// baseline (speedup 1.0000x reference)
#include <cuda_runtime.h>
#include <cstdint>
#include <cstdio>

// Problem constants (fixed by the reference setup)
#define NB 4
#define NH 16
#define SL 2048
#define HD 64
#define TOPKK 128

// Tiling
#define TQ 16      // queries per CTA
#define CK 256     // key chunk per staging step
#define NTHR 256   // threads per CTA

// SMEM layout (bytes)
#define SM_KEYS  0
#define SM_QS    (TQ*SL*4)               // 131072
#define SM_KS    (SM_QS + TQ*HD*4)       // 135168
#define SM_SELI  (SM_KS + CK*HD*4)       // 200704  (sel arrays live after phase1; Ks reused as warp buffers)
#define SM_SELW  (SM_SELI + TQ*TOPKK*4)  // 208896
#define SM_TOTAL (SM_SELW + TQ*TOPKK*4)  // 217088

// Order-preserving float<->uint key transform (monotone increasing)
__device__ __forceinline__ uint32_t f2k(float f) {
    uint32_t b = __float_as_uint(f);
    return b ^ ((b >> 31) ? 0xFFFFFFFFu : 0x80000000u);
}
__device__ __forceinline__ float k2f(uint32_t k) {
    uint32_t b = k ^ ((k >> 31) ? 0x80000000u : 0xFFFFFFFFu);
    return __uint_as_float(b);
}

__global__ void __launch_bounds__(NTHR, 1)
topk_attn_kernel(const float* __restrict__ Qg, const float* __restrict__ Kg,
                 const float* __restrict__ Vg, float* __restrict__ Og)
{
    extern __shared__ char smem[];
    uint32_t* keys = (uint32_t*)(smem + SM_KEYS);   // [TQ][SL] score keys
    float4*   Qs4  = (float4*)(smem + SM_QS);       // [TQ][16] swizzled
    float4*   Ks4  = (float4*)(smem + SM_KS);       // [CK][16] swizzled
    int*      seli = (int*)(smem + SM_SELI);        // [TQ][TOPKK]
    float*    selw = (float*)(smem + SM_SELW);      // [TQ][TOPKK]
    uint32_t* wbase = (uint32_t*)(smem + SM_KS);    // phase-2 per-warp compaction buffers (reuse Ks)

    const int qt  = blockIdx.x;        // 0..127
    const int bh  = blockIdx.y;        // 0..63
    const int tid = threadIdx.x;
    const int qbase  = qt * TQ;
    const int kneed  = qbase + TQ;                    // keys needed for this tile (causal)
    const int nchunk = (kneed + CK - 1) / CK;

    const float* Qb = Qg + ((size_t)bh * SL + qbase) * HD;
    const float* Kb = Kg + (size_t)bh * SL * HD;
    const float* Vb = Vg + (size_t)bh * SL * HD;

    // ---- stage Q tile (swizzled: col' = col ^ (qi>>2)) ----
    {
        int qi = tid >> 4, c = tid & 15;
        float4 v = ((const float4*)(Qb + qi * HD))[c];
        Qs4[qi * 16 + (c ^ (qi >> 2))] = v;
    }
    __syncthreads();

    // ---- Phase 1: scores -> keys[] in SMEM ----
    const int qi0 = (tid & 3) << 2;     // query micro-tile base (4 queries)
    const int qsw = tid & 3;            // Qs swizzle constant = qi0>>2
    const int kg4 = tid >> 2;           // 0..63 key-group
    const int ki0 = kg4 << 2;           // key micro-tile base (4 keys)
    const int ksw = kg4 & 7;            // Ks swizzle constant = (k>>2)&7

    for (int ch = 0; ch < nchunk; ch++) {
        const int kbase = ch * CK;
        // stage K chunk (coalesced, swizzled: col' = col ^ ((row>>2)&7))
        #pragma unroll
        for (int it = 0; it < 16; it++) {
            int idx = it * NTHR + tid;
            int r = idx >> 4, c = idx & 15;
            float4 v = ((const float4*)(Kb + (size_t)(kbase + r) * HD))[c];
            Ks4[r * 16 + (c ^ ((r >> 2) & 7))] = v;
        }
        __syncthreads();

        float acc[4][4] = {};
        #pragma unroll
        for (int d4 = 0; d4 < 16; d4++) {
            float4 qv[4], kv[4];
            #pragma unroll
            for (int i = 0; i < 4; i++) qv[i] = Qs4[(qi0 + i) * 16 + (d4 ^ qsw)];
            #pragma unroll
            for (int j = 0; j < 4; j++) kv[j] = Ks4[(ki0 + j) * 16 + (d4 ^ ksw)];
            #pragma unroll
            for (int i = 0; i < 4; i++)
                #pragma unroll
                for (int j = 0; j < 4; j++) {
                    acc[i][j] = fmaf(qv[i].x, kv[j].x, acc[i][j]);
                    acc[i][j] = fmaf(qv[i].y, kv[j].y, acc[i][j]);
                    acc[i][j] = fmaf(qv[i].z, kv[j].z, acc[i][j]);
                    acc[i][j] = fmaf(qv[i].w, kv[j].w, acc[i][j]);
                }
        }
        // store keys with causal mask (k>q -> -FLT_MAX key, never selected)
        #pragma unroll
        for (int i = 0; i < 4; i++) {
            int qg = qbase + qi0 + i;
            #pragma unroll
            for (int j = 0; j < 4; j++) {
                int kg = kbase + ki0 + j;
                float v = (kg <= qg) ? acc[i][j] : -3.402823466e38f;
                keys[(qi0 + i) * SL + kg] = f2k(v);
            }
        }
        __syncthreads();
    }

    // ---- Phase 2+3: per-query exact top-128 select, softmax, PV gather ----
    const int warp = tid >> 5, lane = tid & 31;
    const unsigned FULL = 0xFFFFFFFFu;
    const uint32_t lmask = (1u << lane) - 1u;
    uint32_t* wbuf = wbase + warp * 2048;     // private per-warp bucket buffer
    const float scale = 0.125f;               // 64^-0.5

    for (int qi = warp; qi < TQ; qi += 8) {
        const int qg = qbase + qi;
        const int n  = qg + 1;                // valid causal keys
        const uint32_t* krow = keys + qi * SL;

        // row max (for softmax stability) == max key
        uint32_t mk = 0;
        for (int i = lane; i < n; i += 32) mk = max(mk, krow[i]);
        mk = __reduce_max_sync(FULL, mk);
        const float mval = k2f(mk);

        uint32_t T = 0; int need_eq = 0;
        if (n > TOPKK) {
            uint32_t prefix = 0; int r = TOPKK;
            // binary radix-descent on top byte, full row
            #pragma unroll
            for (int b = 31; b >= 24; b--) {
                const uint32_t test = prefix | (1u << b);
                const uint32_t hm = ~((1u << b) - 1u);
                int c = 0;
                for (int i = lane; i < n; i += 32)
                    c += ((krow[i] & hm) == test) ? 1 : 0;
                c = __reduce_add_sync(FULL, c);
                if (c >= r) prefix = test; else r -= c;
            }
            // compact elements in the threshold's top-byte bucket
            int m = 0;
            for (int base = 0; base < n; base += 32) {
                int i = base + lane;
                uint32_t k = (i < n) ? krow[i] : 0u;
                bool mt = (i < n) && ((k & 0xFF000000u) == prefix);
                uint32_t bal = __ballot_sync(FULL, mt);
                if (mt) wbuf[m + __popc(bal & lmask)] = k;
                m += __popc(bal);
            }
            // finish remaining 24 bits on the small bucket
            #pragma unroll
            for (int b = 23; b >= 0; b--) {
                const uint32_t test = prefix | (1u << b);
                const uint32_t hm = ~((1u << b) - 1u);
                int c = 0;
                for (int i = lane; i < m; i += 32)
                    c += ((wbuf[i] & hm) == test) ? 1 : 0;
                c = __reduce_add_sync(FULL, c);
                if (c >= r) prefix = test; else r -= c;
            }
            T = prefix;       // exact key of 128th largest
            need_eq = r;      // ties at T to include (lowest indices, matching jax top_k)
        }
        // else: T=0 (< any valid key), need_eq=0 -> select all n

        // weight pass: select, compute exp weights, compact (idx,w), denom
        int* si = seli + qi * TOPKK;
        float* sw = selw + qi * TOPKK;
        int neq = 0, nsel = 0;
        float dsum = 0.f;
        for (int base = 0; base < n; base += 32) {
            int i = base + lane;
            uint32_t k = (i < n) ? krow[i] : 0u;
            bool gt = (i < n) && (k > T);
            bool eq = (i < n) && (k == T);
            uint32_t ebal = __ballot_sync(FULL, eq);
            bool sel = gt || (eq && (neq + __popc(ebal & lmask)) < need_eq);
            uint32_t sbal = __ballot_sync(FULL, sel);
            if (sel) {
                float w = __expf((k2f(k) - mval) * scale);
                int pos = nsel + __popc(sbal & lmask);
                si[pos] = i; sw[pos] = w;
                dsum += w;
            }
            neq  += __popc(ebal);
            nsel += __popc(sbal);
        }
        #pragma unroll
        for (int o = 16; o > 0; o >>= 1) dsum += __shfl_xor_sync(FULL, dsum, o);
        const float inv = 1.f / dsum;

        // PV gather: warp covers 64 dims (lane, lane+32), 4-way unrolled for MLP
        float acc0 = 0.f, acc1 = 0.f;
        const int S = nsel;
        int t = 0;
        for (; t + 4 <= S; t += 4) {
            int i0 = si[t], i1 = si[t+1], i2 = si[t+2], i3 = si[t+3];
            float w0 = sw[t], w1 = sw[t+1], w2 = sw[t+2], w3 = sw[t+3];
            const float* v0 = Vb + (size_t)i0 * HD;
            const float* v1 = Vb + (size_t)i1 * HD;
            const float* v2 = Vb + (size_t)i2 * HD;
            const float* v3 = Vb + (size_t)i3 * HD;
            float a0 = v0[lane], b0 = v0[lane + 32];
            float a1 = v1[lane], b1 = v1[lane + 32];
            float a2 = v2[lane], b2 = v2[lane + 32];
            float a3 = v3[lane], b3 = v3[lane + 32];
            acc0 = fmaf(w0, a0, acc0); acc1 = fmaf(w0, b0, acc1);
            acc0 = fmaf(w1, a1, acc0); acc1 = fmaf(w1, b1, acc1);
            acc0 = fmaf(w2, a2, acc0); acc1 = fmaf(w2, b2, acc1);
            acc0 = fmaf(w3, a3, acc0); acc1 = fmaf(w3, b3, acc1);
        }
        for (; t < S; t++) {
            int i0 = si[t]; float w0 = sw[t];
            const float* v0 = Vb + (size_t)i0 * HD;
            acc0 = fmaf(w0, v0[lane], acc0);
            acc1 = fmaf(w0, v0[lane + 32], acc1);
        }

        float* orow = Og + ((size_t)bh * SL + qg) * HD;
        orow[lane]      = acc0 * inv;
        orow[lane + 32] = acc1 * inv;
    }
}

extern "C" void kernel_launch(void* const* d_in, const int* in_sizes, int n_in,
                              void* d_out, int out_size) {
    (void)in_sizes; (void)n_in; (void)out_size;
    const float* Q = (const float*)d_in[0];
    const float* K = (const float*)d_in[1];
    const float* V = (const float*)d_in[2];
    // d_in[3] = topk (compile-time 128)
    float* O = (float*)d_out;

    cudaFuncSetAttribute(topk_attn_kernel,
                         cudaFuncAttributeMaxDynamicSharedMemorySize, SM_TOTAL);

    dim3 grid(SL / TQ, NB * NH);   // (128, 64)
    topk_attn_kernel<<<grid, NTHR, SM_TOTAL>>>(Q, K, V, O);
}